// round 7
// baseline (speedup 1.0000x reference)
#include <cuda_runtime.h>

#define N_NODES 100000
#define N_EDGES 1600000
#define NB_SCAN 98              // ceil((N_NODES+1)/1024)
#define NEG_SLOPE 0.2f
#define FULLM 0xffffffffu
#define GB_GEMM 1563            // ceil(N_NODES/64)

// ---------------- scratch (device globals; zero-initialized at module load) ----------
// Cross-call invariant: g_deg and g_tstat are zero at the start of every
// kernel_launch call — module-load zero-init covers the first call; k_fill
// re-zeroes them (after their last use) for every later call.
__device__ int      g_deg[N_NODES + 1];
__device__ int      g_rowptr[N_NODES + 1];
__device__ int      g_ord[N_EDGES];       // within-dst-bucket rank of each edge
__device__ unsigned g_tstat[NB_SCAN];     // lookback status: [31:30] flag (1=agg,2=prefix), [29:0] value
__device__ int      g_adj[N_EDGES];
__device__ float    g_h[N_NODES * 64];    // transformed features of current layer
__device__ float    g_feat[N_NODES * 64]; // layer-1 output (input to layer 2)
__device__ float    g_as[N_NODES];
__device__ float    g_ad[N_NODES];

// ---------------- dst histogram + per-edge bucket rank (+ zero out) ----------------
// The atomicAdd return value IS the edge's rank within its dst bucket; saving
// it makes k_fill atomic-free.
__global__ void __launch_bounds__(256) k_hist(const int* __restrict__ ei,
                                              float* __restrict__ out) {
    int e = blockIdx.x * 256 + threadIdx.x;
    if (blockIdx.x == 0 && threadIdx.x < 64) out[threadIdx.x] = 0.0f;
    if (e < N_EDGES) {
        int d = __ldg(&ei[N_EDGES + e]);
        g_ord[e] = atomicAdd(&g_deg[d + 1], 1);
    }
}

// ---------------- smem-staged SIMT outer-product GEMM + attention logits -------------
// Block = 256 threads -> tile of 64 nodes x 64 outputs. Thread (tx=tid&15,
// ty=tid>>4) owns a 4x4 register tile: nodes tx*4..+3, outs ty*4..+3.
// X tile and W are transposed into k-major smem; inner loop per k is
// 2x LDS.128 (conflict-light) + 16 FFMA -> FFMA-pipe bound.
template <int IN>
__global__ void __launch_bounds__(256)
k_gemm(const float* __restrict__ Xext,
       const float* __restrict__ W,
       const float* __restrict__ avsrc,
       const float* __restrict__ avdst) {
    __shared__ float xs[64][68];     // xs[k][node]
    __shared__ float ws[64][68];     // ws[k][out]
    __shared__ float sASP[64][17];   // per-node logit partials over ty
    __shared__ float sADP[64][17];

    const float* X = (IN == 128) ? Xext : (const float*)g_feat;
    const int tid = threadIdx.x;
    const int tx  = tid & 15;
    const int ty  = tid >> 4;
    const int nbase = blockIdx.x * 64;
    const int C = IN / 4;            // float4s per row

    const float4* X4 = (const float4*)X;
    const float4* W4 = (const float4*)W;

    float acc[4][4];
#pragma unroll
    for (int i = 0; i < 4; i++)
#pragma unroll
        for (int o = 0; o < 4; o++) acc[i][o] = 0.f;

#pragma unroll
    for (int ch = 0; ch < IN / 64; ch++) {
        const int kc4 = ch * 16;     // float4 column offset of this k-chunk
        __syncthreads();
        // stage X-tile and W chunk, transposing to k-major.
        // idx bits: [1:0]->c4 low, [7:2]->row, [9:8]->c4 high
        // -> warp covers 8 rows x 4 c4: 64B-coalesced global reads, 2-way STS banks.
#pragma unroll
        for (int it = 0; it < 4; it++) {
            int idx = tid + it * 256;
            int c4  = (idx & 3) | (((idx >> 8) & 3) << 2);
            int r   = (idx >> 2) & 63;
            int xrow = min(nbase + r, N_NODES - 1);     // clamp tail (stores guarded)
            float4 v = __ldg(&X4[(long)xrow * C + kc4 + c4]);
            xs[c4 * 4 + 0][r] = v.x; xs[c4 * 4 + 1][r] = v.y;
            xs[c4 * 4 + 2][r] = v.z; xs[c4 * 4 + 3][r] = v.w;
            float4 wv = __ldg(&W4[(long)r * C + kc4 + c4]);
            ws[c4 * 4 + 0][r] = wv.x; ws[c4 * 4 + 1][r] = wv.y;
            ws[c4 * 4 + 2][r] = wv.z; ws[c4 * 4 + 3][r] = wv.w;
        }
        __syncthreads();

#pragma unroll 4
        for (int kk = 0; kk < 64; kk++) {
            float4 xv = *(const float4*)&xs[kk][tx * 4];   // 4 nodes at this k
            float4 wv = *(const float4*)&ws[kk][ty * 4];   // 4 outs at this k
            acc[0][0] += xv.x * wv.x; acc[0][1] += xv.x * wv.y;
            acc[0][2] += xv.x * wv.z; acc[0][3] += xv.x * wv.w;
            acc[1][0] += xv.y * wv.x; acc[1][1] += xv.y * wv.y;
            acc[1][2] += xv.y * wv.z; acc[1][3] += xv.y * wv.w;
            acc[2][0] += xv.z * wv.x; acc[2][1] += xv.z * wv.y;
            acc[2][2] += xv.z * wv.z; acc[2][3] += xv.z * wv.w;
            acc[3][0] += xv.w * wv.x; acc[3][1] += xv.w * wv.y;
            acc[3][2] += xv.w * wv.z; acc[3][3] += xv.w * wv.w;
        }
    }

    // store h
    float4* H4 = (float4*)g_h;
#pragma unroll
    for (int i = 0; i < 4; i++) {
        int node = nbase + tx * 4 + i;
        if (node < N_NODES)
            H4[(long)node * 16 + ty] =
                make_float4(acc[i][0], acc[i][1], acc[i][2], acc[i][3]);
    }

    // attention logit partials: as = h . a_src, ad = h . a_dst (deterministic tree)
    float4 sv = __ldg((const float4*)avsrc + ty);
    float4 dv = __ldg((const float4*)avdst + ty);
#pragma unroll
    for (int i = 0; i < 4; i++) {
        float sp = acc[i][0] * sv.x + acc[i][1] * sv.y + acc[i][2] * sv.z + acc[i][3] * sv.w;
        float dp = acc[i][0] * dv.x + acc[i][1] * dv.y + acc[i][2] * dv.z + acc[i][3] * dv.w;
        sASP[tx * 4 + i][ty] = sp;
        sADP[tx * 4 + i][ty] = dp;
    }
    __syncthreads();
    if (tid < 64) {
        int node = nbase + tid;
        if (node < N_NODES) {
            float s = 0.f, d = 0.f;
#pragma unroll
            for (int j = 0; j < 16; j++) { s += sASP[tid][j]; d += sADP[tid][j]; }
            g_as[node] = s;
            g_ad[node] = d;
        }
    }
}

// ---------------- single-kernel decoupled-lookback scan of g_deg -> g_rowptr ----------
// 98 tiles of 1024; 98 blocks co-resident so polling always makes progress.
// Status word packs flag+value so the single 32-bit atomic publish needs no fence.
__global__ void __launch_bounds__(1024) k_scan() {
    __shared__ int s[1024];
    __shared__ int s_prefix;
    const int t = threadIdx.x;
    const int tile = blockIdx.x;
    const int i = tile * 1024 + t;
    int v = (i <= N_NODES) ? g_deg[i] : 0;
    s[t] = v;
    __syncthreads();
    for (int off = 1; off < 1024; off <<= 1) {
        int x = (t >= off) ? s[t - off] : 0;
        __syncthreads();
        s[t] += x;
        __syncthreads();
    }
    const int inc = s[t];
    const int total = s[1023];

    if (t == 0) {
        if (tile == 0) {
            atomicExch(&g_tstat[0], (2u << 30) | (unsigned)total);
            s_prefix = 0;
        } else {
            atomicExch(&g_tstat[tile], (1u << 30) | (unsigned)total);
            int prefix = 0;
            int p = tile - 1;
            while (true) {
                unsigned st = *(volatile unsigned*)&g_tstat[p];
                unsigned f = st >> 30;
                if (f == 0u) continue;
                prefix += (int)(st & 0x3FFFFFFFu);
                if (f == 2u) break;
                p--;
            }
            atomicExch(&g_tstat[tile], (2u << 30) | (unsigned)(prefix + total));
            s_prefix = prefix;
        }
    }
    __syncthreads();
    const int val = inc + s_prefix;
    if (i <= N_NODES) g_rowptr[i] = val;
}

// ---------------- atomic-free adjacency fill + cleanup for next call ----------------
// pos = rowptr[dst] + precomputed bucket rank: loads + one scattered store only.
__global__ void __launch_bounds__(512) k_fill(const int* __restrict__ ei) {
    int gid = blockIdx.x * 512 + threadIdx.x;
    if (gid <= N_NODES) g_deg[gid] = 0;       // reset for next kernel_launch call
    if (gid < NB_SCAN) g_tstat[gid] = 0u;     // reset lookback status
    if (gid < N_EDGES) {
        int d   = __ldg(&ei[N_EDGES + gid]);
        int pos = __ldg(&g_rowptr[d]) + g_ord[gid];
        g_adj[pos] = __ldg(&ei[gid]);
    }
}

// ---------------- half-warp-per-node softmax aggregation (atomic-free) ---------------
// 16 lanes own one node; lane l holds features [4l, 4l+4). One LDG.128 across
// the 16 lanes fetches a full 256B h-row per edge; full chunks run a straight-
// line 16-edge body with 8 gathers batched per group (16 LDG.128 in flight).
// exp-max subtraction omitted: logits are O(10) so fp32 exp cannot overflow
// and the ratio is unchanged.
// mode 1: relu + store g_feat; mode 2: fused global mean pool into out.
__global__ void __launch_bounds__(512)
k_agg(const float* __restrict__ b, float* __restrict__ out, int mode) {
    __shared__ float sred[64];
    if (mode == 2) {
        if (threadIdx.x < 64) sred[threadIdx.x] = 0.f;
        __syncthreads();
    }
    const int lane = threadIdx.x & 31;
    const int l = lane & 15;
    const unsigned hm = 0xFFFFu << (lane & 16);
    const int node = (blockIdx.x * 512 + threadIdx.x) >> 4;   // exact: 3125*512/16 = 100000

    const float4* H4 = (const float4*)g_h;
    const float adn = g_ad[node];
    float e0 = g_as[node] + adn;
    e0 = (e0 > 0.f) ? e0 : NEG_SLOPE * e0;
    const float exs = __expf(e0);                 // self-loop term

    float4 hv = __ldg(H4 + (long)node * 16 + l);
    float4 acc = make_float4(exs * hv.x, exs * hv.y, exs * hv.z, exs * hv.w);
    float dsum = 0.f;

    const int beg = __ldg(&g_rowptr[node]);
    const int end = __ldg(&g_rowptr[node + 1]);
    for (int k = beg; k < end; k += 16) {
        int idx = k + l;
        int s = 0;
        float ex = 0.f;
        if (idx < end) {
            s = __ldg(&g_adj[idx]);
            float e = __ldg(&g_as[s]) + adn;
            e = (e > 0.f) ? e : NEG_SLOPE * e;
            ex = __expf(e);
        }
        dsum += ex;
        const int cnt = min(16, end - k);
        if (cnt == 16) {
#pragma unroll
            for (int jg = 0; jg < 16; jg += 8) {
                int   sj[8]; float xj[8]; float4 hj[8];
#pragma unroll
                for (int u = 0; u < 8; u++) {
                    sj[u] = __shfl_sync(hm, s, jg + u, 16);
                    xj[u] = __shfl_sync(hm, ex, jg + u, 16);
                }
#pragma unroll
                for (int u = 0; u < 8; u++)
                    hj[u] = __ldg(H4 + (long)sj[u] * 16 + l);
#pragma unroll
                for (int u = 0; u < 8; u++) {
                    acc.x += xj[u] * hj[u].x; acc.y += xj[u] * hj[u].y;
                    acc.z += xj[u] * hj[u].z; acc.w += xj[u] * hj[u].w;
                }
            }
        } else {
            for (int j = 0; j < cnt; j++) {
                int   sj = __shfl_sync(hm, s, j, 16);
                float xj = __shfl_sync(hm, ex, j, 16);
                float4 hj = __ldg(H4 + (long)sj * 16 + l);
                acc.x += xj * hj.x; acc.y += xj * hj.y; acc.z += xj * hj.z; acc.w += xj * hj.w;
            }
        }
    }
#pragma unroll
    for (int m = 8; m; m >>= 1) dsum += __shfl_xor_sync(hm, dsum, m, 16);

    const float inv = 1.0f / (dsum + exs);
    float4 bb = __ldg((const float4*)b + l);
    float4 r = make_float4(acc.x * inv + bb.x, acc.y * inv + bb.y,
                           acc.z * inv + bb.z, acc.w * inv + bb.w);

    if (mode == 1) {
        r.x = fmaxf(r.x, 0.f); r.y = fmaxf(r.y, 0.f);
        r.z = fmaxf(r.z, 0.f); r.w = fmaxf(r.w, 0.f);
        ((float4*)g_feat)[(long)node * 16 + l] = r;
    } else {
        // fused global mean pool
        __syncwarp(FULLM);
        r.x += __shfl_xor_sync(FULLM, r.x, 16);
        r.y += __shfl_xor_sync(FULLM, r.y, 16);
        r.z += __shfl_xor_sync(FULLM, r.z, 16);
        r.w += __shfl_xor_sync(FULLM, r.w, 16);
        if (lane < 16) {
            atomicAdd(&sred[4 * l + 0], r.x);
            atomicAdd(&sred[4 * l + 1], r.y);
            atomicAdd(&sred[4 * l + 2], r.z);
            atomicAdd(&sred[4 * l + 3], r.w);
        }
        __syncthreads();
        if (threadIdx.x < 64)
            atomicAdd(&out[threadIdx.x], sred[threadIdx.x] * (1.0f / N_NODES));
    }
}

// ---------------- launch (serial; saturating grids don't benefit from streams) ------
extern "C" void kernel_launch(void* const* d_in, const int* in_sizes, int n_in,
                              void* d_out, int out_size) {
    const float* x   = (const float*)d_in[0];
    const int*   ei  = (const int*)d_in[1];
    // d_in[2] = edge_attr (unused; GATConv edge_dim=None)
    const float* W1  = (const float*)d_in[3];
    const float* as1 = (const float*)d_in[4];
    const float* ad1 = (const float*)d_in[5];
    const float* b1  = (const float*)d_in[6];
    const float* W2  = (const float*)d_in[7];
    const float* as2 = (const float*)d_in[8];
    const float* ad2 = (const float*)d_in[9];
    const float* b2  = (const float*)d_in[10];
    float* out = (float*)d_out;

    k_hist<<<6250, 256>>>(ei, out);            // deg histogram + bucket ranks
    k_gemm<128><<<GB_GEMM, 256>>>(x, W1, as1, ad1);
    k_scan<<<NB_SCAN, 1024>>>();               // rowptr
    k_fill<<<3125, 512>>>(ei);                 // atomic-free adjacency fill
    k_agg<<<3125, 512>>>(b1, out, 1);          // layer-1 aggregation
    k_gemm<64><<<GB_GEMM, 256>>>(nullptr, W2, as2, ad2);
    k_agg<<<3125, 512>>>(b2, out, 2);          // layer-2 aggregation + mean pool
}

// round 8
// speedup vs baseline: 1.2421x; 1.2421x over previous
#include <cuda_runtime.h>

#define N_NODES 100000
#define N_EDGES 1600000
#define NB_SCAN 98              // ceil((N_NODES+1)/1024)
#define NEG_SLOPE 0.2f
#define FULLM 0xffffffffu
#define GB_GEMM 1563            // ceil(N_NODES/64)
#define GB_HIST 6250            // ceil(N_EDGES/256)

// ---------------- scratch (device globals; zero-initialized at module load) ----------
// Cross-call invariant: g_deg and g_tstat are zero at the start of every
// kernel_launch call — module-load zero-init covers the first call; k_fill
// re-zeroes them (after their last use) for every later call.
__device__ int      g_deg[N_NODES + 1];
__device__ int      g_rowptr[N_NODES + 1];
__device__ int      g_ord[N_EDGES];       // within-dst-bucket rank of each edge
__device__ unsigned g_tstat[NB_SCAN];     // lookback status: [31:30] flag (1=agg,2=prefix), [29:0] value
__device__ int      g_adj[N_EDGES];
__device__ float    g_h[N_NODES * 64];    // transformed features of current layer
__device__ float    g_feat[N_NODES * 64]; // layer-1 output (input to layer 2)
__device__ float    g_as[N_NODES];
__device__ float    g_ad[N_NODES];

// ---------------- smem-staged SIMT outer-product GEMM + attention logits -------------
// Block = 256 threads -> tile of 64 nodes x 64 outputs. Thread (tx=tid&15,
// ty=tid>>4) owns a 4x4 register tile: nodes tx*4..+3, outs ty*4..+3.
// X tile and W are transposed into k-major smem; inner loop per k is
// 2x LDS.128 (conflict-light) + 16 FFMA -> FFMA-pipe bound.
// HIST: blocks >= GB_GEMM run the dst-degree histogram + bucket-rank capture
// (LSU/atomic-bound, overlaps the FMA-bound gemm blocks for ~free). The
// atomicAdd return value IS the edge's rank within its dst bucket, which
// makes k_fill atomic-free.
template <int IN, bool HIST>
__global__ void __launch_bounds__(256)
k_gemm(const float* __restrict__ Xext,
       const float* __restrict__ W,
       const float* __restrict__ avsrc,
       const float* __restrict__ avdst,
       const int* __restrict__ ei,
       float* __restrict__ out) {
    if (HIST && blockIdx.x >= GB_GEMM) {
        int e = (blockIdx.x - GB_GEMM) * 256 + threadIdx.x;
        if (e < N_EDGES) {
            int d = __ldg(&ei[N_EDGES + e]);
            g_ord[e] = atomicAdd(&g_deg[d + 1], 1);
        }
        return;
    }
    __shared__ float xs[64][68];     // xs[k][node]
    __shared__ float ws[64][68];     // ws[k][out]
    __shared__ float sASP[64][17];   // per-node logit partials over ty
    __shared__ float sADP[64][17];

    const float* X = (IN == 128) ? Xext : (const float*)g_feat;
    const int tid = threadIdx.x;
    const int tx  = tid & 15;
    const int ty  = tid >> 4;
    const int nbase = blockIdx.x * 64;
    const int C = IN / 4;            // float4s per row

    if (!HIST && blockIdx.x == 0 && tid < 64) out[tid] = 0.0f;

    const float4* X4 = (const float4*)X;
    const float4* W4 = (const float4*)W;

    float acc[4][4];
#pragma unroll
    for (int i = 0; i < 4; i++)
#pragma unroll
        for (int o = 0; o < 4; o++) acc[i][o] = 0.f;

#pragma unroll
    for (int ch = 0; ch < IN / 64; ch++) {
        const int kc4 = ch * 16;     // float4 column offset of this k-chunk
        __syncthreads();
        // stage X-tile and W chunk, transposing to k-major.
        // idx bits: [1:0]->c4 low, [7:2]->row, [9:8]->c4 high
        // -> warp covers 8 rows x 4 c4: 64B-coalesced global reads, 2-way STS banks.
#pragma unroll
        for (int it = 0; it < 4; it++) {
            int idx = tid + it * 256;
            int c4  = (idx & 3) | (((idx >> 8) & 3) << 2);
            int r   = (idx >> 2) & 63;
            int xrow = min(nbase + r, N_NODES - 1);     // clamp tail (stores guarded)
            float4 v = __ldg(&X4[(long)xrow * C + kc4 + c4]);
            xs[c4 * 4 + 0][r] = v.x; xs[c4 * 4 + 1][r] = v.y;
            xs[c4 * 4 + 2][r] = v.z; xs[c4 * 4 + 3][r] = v.w;
            float4 wv = __ldg(&W4[(long)r * C + kc4 + c4]);
            ws[c4 * 4 + 0][r] = wv.x; ws[c4 * 4 + 1][r] = wv.y;
            ws[c4 * 4 + 2][r] = wv.z; ws[c4 * 4 + 3][r] = wv.w;
        }
        __syncthreads();

#pragma unroll 4
        for (int kk = 0; kk < 64; kk++) {
            float4 xv = *(const float4*)&xs[kk][tx * 4];   // 4 nodes at this k
            float4 wv = *(const float4*)&ws[kk][ty * 4];   // 4 outs at this k
            acc[0][0] += xv.x * wv.x; acc[0][1] += xv.x * wv.y;
            acc[0][2] += xv.x * wv.z; acc[0][3] += xv.x * wv.w;
            acc[1][0] += xv.y * wv.x; acc[1][1] += xv.y * wv.y;
            acc[1][2] += xv.y * wv.z; acc[1][3] += xv.y * wv.w;
            acc[2][0] += xv.z * wv.x; acc[2][1] += xv.z * wv.y;
            acc[2][2] += xv.z * wv.z; acc[2][3] += xv.z * wv.w;
            acc[3][0] += xv.w * wv.x; acc[3][1] += xv.w * wv.y;
            acc[3][2] += xv.w * wv.z; acc[3][3] += xv.w * wv.w;
        }
    }

    // store h
    float4* H4 = (float4*)g_h;
#pragma unroll
    for (int i = 0; i < 4; i++) {
        int node = nbase + tx * 4 + i;
        if (node < N_NODES)
            H4[(long)node * 16 + ty] =
                make_float4(acc[i][0], acc[i][1], acc[i][2], acc[i][3]);
    }

    // attention logit partials: as = h . a_src, ad = h . a_dst (deterministic tree)
    float4 sv = __ldg((const float4*)avsrc + ty);
    float4 dv = __ldg((const float4*)avdst + ty);
#pragma unroll
    for (int i = 0; i < 4; i++) {
        float sp = acc[i][0] * sv.x + acc[i][1] * sv.y + acc[i][2] * sv.z + acc[i][3] * sv.w;
        float dp = acc[i][0] * dv.x + acc[i][1] * dv.y + acc[i][2] * dv.z + acc[i][3] * dv.w;
        sASP[tx * 4 + i][ty] = sp;
        sADP[tx * 4 + i][ty] = dp;
    }
    __syncthreads();
    if (tid < 64) {
        int node = nbase + tid;
        if (node < N_NODES) {
            float s = 0.f, d = 0.f;
#pragma unroll
            for (int j = 0; j < 16; j++) { s += sASP[tid][j]; d += sADP[tid][j]; }
            g_as[node] = s;
            g_ad[node] = d;
        }
    }
}

// ---------------- single-kernel decoupled-lookback scan of g_deg -> g_rowptr ----------
// 98 tiles of 1024; 98 blocks co-resident so polling always makes progress.
// Status word packs flag+value so the single 32-bit atomic publish needs no fence.
__global__ void __launch_bounds__(1024) k_scan() {
    __shared__ int s[1024];
    __shared__ int s_prefix;
    const int t = threadIdx.x;
    const int tile = blockIdx.x;
    const int i = tile * 1024 + t;
    int v = (i <= N_NODES) ? g_deg[i] : 0;
    s[t] = v;
    __syncthreads();
    for (int off = 1; off < 1024; off <<= 1) {
        int x = (t >= off) ? s[t - off] : 0;
        __syncthreads();
        s[t] += x;
        __syncthreads();
    }
    const int inc = s[t];
    const int total = s[1023];

    if (t == 0) {
        if (tile == 0) {
            atomicExch(&g_tstat[0], (2u << 30) | (unsigned)total);
            s_prefix = 0;
        } else {
            atomicExch(&g_tstat[tile], (1u << 30) | (unsigned)total);
            int prefix = 0;
            int p = tile - 1;
            while (true) {
                unsigned st = *(volatile unsigned*)&g_tstat[p];
                unsigned f = st >> 30;
                if (f == 0u) continue;
                prefix += (int)(st & 0x3FFFFFFFu);
                if (f == 2u) break;
                p--;
            }
            atomicExch(&g_tstat[tile], (2u << 30) | (unsigned)(prefix + total));
            s_prefix = prefix;
        }
    }
    __syncthreads();
    const int val = inc + s_prefix;
    if (i <= N_NODES) g_rowptr[i] = val;
}

// ---------------- atomic-free adjacency fill + cleanup for next call ----------------
// pos = rowptr[dst] + precomputed bucket rank: loads + one scattered store only.
__global__ void __launch_bounds__(512) k_fill(const int* __restrict__ ei) {
    int gid = blockIdx.x * 512 + threadIdx.x;
    if (gid <= N_NODES) g_deg[gid] = 0;       // reset for next kernel_launch call
    if (gid < NB_SCAN) g_tstat[gid] = 0u;     // reset lookback status
    if (gid < N_EDGES) {
        int d   = __ldg(&ei[N_EDGES + gid]);
        int pos = __ldg(&g_rowptr[d]) + g_ord[gid];
        g_adj[pos] = __ldg(&ei[gid]);
    }
}

// ---------------- half-warp-per-node softmax aggregation (atomic-free) ---------------
// 16 lanes own one node; lane l holds features [4l, 4l+4). One LDG.128 across
// the 16 lanes fetches a full 256B h-row per edge; gathers batched 4-wide
// (8 LDG.128 in flight per warp). exp-max subtraction omitted: logits are
// O(10) so fp32 exp cannot overflow and the ratio is unchanged.
// mode 1: relu + store g_feat; mode 2: fused global mean pool into out.
__global__ void __launch_bounds__(512)
k_agg(const float* __restrict__ b, float* __restrict__ out, int mode) {
    __shared__ float sred[64];
    if (mode == 2) {
        if (threadIdx.x < 64) sred[threadIdx.x] = 0.f;
        __syncthreads();
    }
    const int lane = threadIdx.x & 31;
    const int l = lane & 15;
    const unsigned hm = 0xFFFFu << (lane & 16);
    const int node = (blockIdx.x * 512 + threadIdx.x) >> 4;   // exact: 3125*512/16 = 100000

    const float4* H4 = (const float4*)g_h;
    const float adn = g_ad[node];
    float e0 = g_as[node] + adn;
    e0 = (e0 > 0.f) ? e0 : NEG_SLOPE * e0;
    const float exs = __expf(e0);                 // self-loop term

    float4 hv = __ldg(H4 + (long)node * 16 + l);
    float4 acc = make_float4(exs * hv.x, exs * hv.y, exs * hv.z, exs * hv.w);
    float dsum = 0.f;

    const int beg = __ldg(&g_rowptr[node]);
    const int end = __ldg(&g_rowptr[node + 1]);
    for (int k = beg; k < end; k += 16) {
        int idx = k + l;
        int s = 0;
        float ex = 0.f;
        if (idx < end) {
            s = __ldg(&g_adj[idx]);
            float e = __ldg(&g_as[s]) + adn;
            e = (e > 0.f) ? e : NEG_SLOPE * e;
            ex = __expf(e);
        }
        dsum += ex;
        const int cnt = min(16, end - k);
        int j = 0;
        for (; j + 4 <= cnt; j += 4) {
            int   s0 = __shfl_sync(hm, s, j, 16);
            int   s1 = __shfl_sync(hm, s, j + 1, 16);
            int   s2 = __shfl_sync(hm, s, j + 2, 16);
            int   s3 = __shfl_sync(hm, s, j + 3, 16);
            float x0 = __shfl_sync(hm, ex, j, 16);
            float x1 = __shfl_sync(hm, ex, j + 1, 16);
            float x2 = __shfl_sync(hm, ex, j + 2, 16);
            float x3 = __shfl_sync(hm, ex, j + 3, 16);
            float4 h0 = __ldg(H4 + (long)s0 * 16 + l);
            float4 h1 = __ldg(H4 + (long)s1 * 16 + l);
            float4 h2 = __ldg(H4 + (long)s2 * 16 + l);
            float4 h3 = __ldg(H4 + (long)s3 * 16 + l);
            acc.x += x0 * h0.x; acc.y += x0 * h0.y; acc.z += x0 * h0.z; acc.w += x0 * h0.w;
            acc.x += x1 * h1.x; acc.y += x1 * h1.y; acc.z += x1 * h1.z; acc.w += x1 * h1.w;
            acc.x += x2 * h2.x; acc.y += x2 * h2.y; acc.z += x2 * h2.z; acc.w += x2 * h2.w;
            acc.x += x3 * h3.x; acc.y += x3 * h3.y; acc.z += x3 * h3.z; acc.w += x3 * h3.w;
        }
        for (; j < cnt; j++) {
            int   sj = __shfl_sync(hm, s, j, 16);
            float xj = __shfl_sync(hm, ex, j, 16);
            float4 hj = __ldg(H4 + (long)sj * 16 + l);
            acc.x += xj * hj.x; acc.y += xj * hj.y; acc.z += xj * hj.z; acc.w += xj * hj.w;
        }
    }
#pragma unroll
    for (int m = 8; m; m >>= 1) dsum += __shfl_xor_sync(hm, dsum, m, 16);

    const float inv = 1.0f / (dsum + exs);
    float4 bb = __ldg((const float4*)b + l);
    float4 r = make_float4(acc.x * inv + bb.x, acc.y * inv + bb.y,
                           acc.z * inv + bb.z, acc.w * inv + bb.w);

    if (mode == 1) {
        r.x = fmaxf(r.x, 0.f); r.y = fmaxf(r.y, 0.f);
        r.z = fmaxf(r.z, 0.f); r.w = fmaxf(r.w, 0.f);
        ((float4*)g_feat)[(long)node * 16 + l] = r;
    } else {
        // fused global mean pool
        __syncwarp(FULLM);
        r.x += __shfl_xor_sync(FULLM, r.x, 16);
        r.y += __shfl_xor_sync(FULLM, r.y, 16);
        r.z += __shfl_xor_sync(FULLM, r.z, 16);
        r.w += __shfl_xor_sync(FULLM, r.w, 16);
        if (lane < 16) {
            atomicAdd(&sred[4 * l + 0], r.x);
            atomicAdd(&sred[4 * l + 1], r.y);
            atomicAdd(&sred[4 * l + 2], r.z);
            atomicAdd(&sred[4 * l + 3], r.w);
        }
        __syncthreads();
        if (threadIdx.x < 64)
            atomicAdd(&out[threadIdx.x], sred[threadIdx.x] * (1.0f / N_NODES));
    }
}

// ---------------- launch ----------------
extern "C" void kernel_launch(void* const* d_in, const int* in_sizes, int n_in,
                              void* d_out, int out_size) {
    const float* x   = (const float*)d_in[0];
    const int*   ei  = (const int*)d_in[1];
    // d_in[2] = edge_attr (unused; GATConv edge_dim=None)
    const float* W1  = (const float*)d_in[3];
    const float* as1 = (const float*)d_in[4];
    const float* ad1 = (const float*)d_in[5];
    const float* b1  = (const float*)d_in[6];
    const float* W2  = (const float*)d_in[7];
    const float* as2 = (const float*)d_in[8];
    const float* ad2 = (const float*)d_in[9];
    const float* b2  = (const float*)d_in[10];
    float* out = (float*)d_out;

    // (0) layer-1 gemm + dst histogram/rank capture (fused, complementary pipes)
    k_gemm<128, true><<<GB_GEMM + GB_HIST, 256>>>(x, W1, as1, ad1, ei, out);
    // (1) rowptr via single-kernel decoupled lookback scan
    k_scan<<<NB_SCAN, 1024>>>();
    // (2) atomic-free adjacency fill + scratch reset for next call
    k_fill<<<3125, 512>>>(ei);
    // (3) layer-1 aggregation
    k_agg<<<3125, 512>>>(b1, out, 1);
    // (4) layer-2 gemm (+ zero out)
    k_gemm<64, false><<<GB_GEMM, 256>>>(nullptr, W2, as2, ad2, nullptr, out);
    // (5) layer-2 aggregation + fused global mean pool
    k_agg<<<3125, 512>>>(b2, out, 2);
}